// round 1
// baseline (speedup 1.0000x reference)
#include <cuda_runtime.h>

#define N_NODES_MAX 100000
#define F 64
#define N_GRAPHS 64

// ---------------- scratch (static device globals; no allocs allowed) -------
__device__ float g_agg[(size_t)N_NODES_MAX * F];   // 25.6 MB
__device__ float g_h[(size_t)N_NODES_MAX * F];     // 25.6 MB
__device__ float g_sum[N_GRAPHS];
__device__ float g_cnt[N_GRAPHS];
__device__ int   g_e64;   // 1 if edge_index is int64, else int32
__device__ int   g_b64;   // 1 if batch is int64, else int32

// ---------------- packed f32x2 helpers (FFMA2 path, sm_103a) ---------------
__device__ __forceinline__ unsigned long long pack2(float a, float b) {
    unsigned long long r;
    asm("mov.b64 %0, {%1, %2};" : "=l"(r) : "f"(a), "f"(b));
    return r;
}
__device__ __forceinline__ unsigned long long splat2(float a) {
    unsigned long long r;
    asm("mov.b64 %0, {%1, %1};" : "=l"(r) : "f"(a));
    return r;
}
__device__ __forceinline__ void unpack2(unsigned long long v, float& a, float& b) {
    asm("mov.b64 {%0, %1}, %2;" : "=f"(a), "=f"(b) : "l"(v));
}
__device__ __forceinline__ unsigned long long ffma2(unsigned long long a,
                                                    unsigned long long b,
                                                    unsigned long long c) {
    unsigned long long r;
    asm("fma.rn.f32x2 %0, %1, %2, %3;" : "=l"(r) : "l"(a), "l"(b), "l"(c));
    return r;
}

// ---------------- dtype detection (int64 vs int32 indices) -----------------
__global__ void detect_kernel(const void* __restrict__ ei,
                              const void* __restrict__ batch, int nNodes) {
    if (threadIdx.x != 0 || blockIdx.x != 0) return;
    // edge_index: check first 4 int64-views. If data is really int32, the
    // high word is a random index in [0,100000) -> value is huge -> not 64-bit.
    const long long* p = (const long long*)ei;
    bool ok = true;
    for (int i = 0; i < 4; i++) {
        long long v = p[i];
        if (v < 0 || v >= N_NODES_MAX) ok = false;
    }
    g_e64 = ok ? 1 : 0;
    // batch: sorted, tail values ~63. Check int64-views just below N/2 (safe
    // for both interpretations). int32 data packs two ~63s -> huge value.
    const long long* q = (const long long*)batch;
    int M = nNodes / 2;
    bool okb = true;
    for (int i = M - 4; i < M; i++) {
        long long v = q[i];
        if (v < 0 || v >= N_GRAPHS) okb = false;
    }
    g_b64 = okb ? 1 : 0;
}

// ---------------- zero agg (+ pool accumulators) ----------------------------
__global__ void zero_agg_kernel(int n4) {
    int i = blockIdx.x * blockDim.x + threadIdx.x;
    float4* p = (float4*)g_agg;
    if (i < n4) p[i] = make_float4(0.f, 0.f, 0.f, 0.f);
    if (blockIdx.x == 0 && threadIdx.x < N_GRAPHS) {
        g_sum[threadIdx.x] = 0.f;
        g_cnt[threadIdx.x] = 0.f;
    }
}

// ---------------- edge scatter-add: agg[dst] += feat[src] ------------------
// 16 threads per edge; each handles one float4 of the 64-float row.
// Vectorized global reduction (red.global.add.v4.f32, sm_90+).
__global__ void __launch_bounds__(256) scatter_kernel(
    const float* __restrict__ feat, const void* __restrict__ ei, int nE) {
    long long t = (long long)blockIdx.x * blockDim.x + threadIdx.x;
    int e = (int)(t >> 4);
    if (e >= nE) return;
    int c = (int)(t & 15);
    int is64 = g_e64;
    int s, d;
    if (is64) {
        const long long* p = (const long long*)ei;
        s = (int)p[e];
        d = (int)p[nE + e];
    } else {
        const int* p = (const int*)ei;
        s = p[e];
        d = p[nE + e];
    }
    float4 v = *((const float4*)(feat + (size_t)s * F) + c);
    const float* dp = g_agg + (size_t)d * F + (size_t)c * 4;
    asm volatile("red.global.add.v4.f32 [%0], {%1, %2, %3, %4};"
                 :: "l"(dp), "f"(v.x), "f"(v.y), "f"(v.z), "f"(v.w)
                 : "memory");
}

// ---------------- 64->64 dense layer + ReLU (warp-cooperative) -------------
// Lane computes outputs j = 2*lane, 2*lane+1 via packed f32x2 FMAs.
__device__ __forceinline__ float2 dense64_relu(const float* __restrict__ sW,
                                               const float* __restrict__ sb,
                                               const float* __restrict__ sIn,
                                               int lane) {
    unsigned long long acc = pack2(sb[2 * lane], sb[2 * lane + 1]);
    const float4* inF = (const float4*)sIn;
    const float* wr0 = sW + 2 * lane;
#pragma unroll
    for (int k4 = 0; k4 < 16; k4++) {
        float4 tv = inF[k4];
        const float* wr = wr0 + k4 * 4 * F;
        acc = ffma2(*(const unsigned long long*)(wr),          splat2(tv.x), acc);
        acc = ffma2(*(const unsigned long long*)(wr + F),      splat2(tv.y), acc);
        acc = ffma2(*(const unsigned long long*)(wr + 2 * F),  splat2(tv.z), acc);
        acc = ffma2(*(const unsigned long long*)(wr + 3 * F),  splat2(tv.w), acc);
    }
    float a, b;
    unpack2(acc, a, b);
    return make_float2(fmaxf(a, 0.f), fmaxf(b, 0.f));
}

// ---------------- fused GIN MLP: out = relu(relu((x+agg)@W1+b1)@W2+b2) -----
// POOL variant skips writing h and accumulates dot(h2, fcW) per graph.
template <bool POOL>
__global__ void __launch_bounds__(256) mlp_kernel(
    const float* __restrict__ xin,
    const float* __restrict__ W1, const float* __restrict__ b1,
    const float* __restrict__ W2, const float* __restrict__ b2,
    float* __restrict__ hout,
    const void* __restrict__ batch,
    const float* __restrict__ fcW,
    int nNodes) {
    __shared__ float sW1[F * F];
    __shared__ float sW2[F * F];
    __shared__ float sb1[F], sb2[F], sfc[F];
    __shared__ __align__(16) float sIn[8][F];

    int tid = threadIdx.x;
    {
        float4* d1 = (float4*)sW1;
        const float4* s1 = (const float4*)W1;
        float4* d2 = (float4*)sW2;
        const float4* s2 = (const float4*)W2;
        for (int i = tid; i < F * F / 4; i += 256) {
            d1[i] = s1[i];
            d2[i] = s2[i];
        }
        if (tid < F) {
            sb1[tid] = b1[tid];
            sb2[tid] = b2[tid];
            sfc[tid] = POOL ? fcW[tid] : 0.f;
        }
    }
    __syncthreads();

    int warp = tid >> 5, lane = tid & 31;
    int b64 = POOL ? g_b64 : 0;
    const int NPW = 8;  // nodes per warp
    int base = (blockIdx.x * 8 + warp) * NPW;

    for (int it = 0; it < NPW; it++) {
        int node = base + it;
        if (node >= nNodes) break;  // uniform within warp
        size_t off = (size_t)node * F;

        float t0 = xin[off + lane]      + g_agg[off + lane];
        float t1 = xin[off + lane + 32] + g_agg[off + lane + 32];
        __syncwarp();
        sIn[warp][lane] = t0;
        sIn[warp][lane + 32] = t1;
        __syncwarp();

        float2 z1 = dense64_relu(sW1, sb1, sIn[warp], lane);
        __syncwarp();
        sIn[warp][2 * lane] = z1.x;
        sIn[warp][2 * lane + 1] = z1.y;
        __syncwarp();

        float2 z2 = dense64_relu(sW2, sb2, sIn[warp], lane);

        if (POOL) {
            float s = z2.x * sfc[2 * lane] + z2.y * sfc[2 * lane + 1];
#pragma unroll
            for (int o = 16; o > 0; o >>= 1)
                s += __shfl_down_sync(0xffffffffu, s, o);
            if (lane == 0) {
                int g = b64 ? (int)((const long long*)batch)[node]
                            : ((const int*)batch)[node];
                atomicAdd(&g_sum[g], s);
                atomicAdd(&g_cnt[g], 1.f);
            }
        } else {
            ((float2*)(hout + off))[lane] = z2;
        }
    }
}

// ---------------- final: out[g] = sum/cnt + fcb -----------------------------
__global__ void final_kernel(float* __restrict__ out,
                             const float* __restrict__ fcb) {
    int g = threadIdx.x;
    if (g < N_GRAPHS)
        out[g] = g_sum[g] / fmaxf(g_cnt[g], 1.f) + fcb[0];
}

// ---------------- launch -----------------------------------------------------
extern "C" void kernel_launch(void* const* d_in, const int* in_sizes, int n_in,
                              void* d_out, int out_size) {
    const float* x    = (const float*)d_in[0];
    const void*  ei   = d_in[1];
    const void*  bat  = d_in[2];
    const float* W1_0 = (const float*)d_in[3];
    const float* b1_0 = (const float*)d_in[4];
    const float* W2_0 = (const float*)d_in[5];
    const float* b2_0 = (const float*)d_in[6];
    const float* W1_1 = (const float*)d_in[7];
    const float* b1_1 = (const float*)d_in[8];
    const float* W2_1 = (const float*)d_in[9];
    const float* b2_1 = (const float*)d_in[10];
    const float* fcW  = (const float*)d_in[11];
    const float* fcb  = (const float*)d_in[12];

    int E = in_sizes[1] / 2;
    int N = in_sizes[2];

    float* h_p = nullptr;
    cudaGetSymbolAddress((void**)&h_p, g_h);  // host-side, capture-safe

    int n4 = N * F / 4;
    int zb = (n4 + 255) / 256;
    long long sthreads = (long long)E * 16;
    int sb = (int)((sthreads + 255) / 256);
    int mb = (N + 63) / 64;

    detect_kernel<<<1, 32>>>(ei, bat, N);

    // ---- layer 1 ----
    zero_agg_kernel<<<zb, 256>>>(n4);
    scatter_kernel<<<sb, 256>>>(x, ei, E);
    mlp_kernel<false><<<mb, 256>>>(x, W1_0, b1_0, W2_0, b2_0, h_p, bat, fcW, N);

    // ---- layer 2 (+ fused pooling projection) ----
    zero_agg_kernel<<<zb, 256>>>(n4);
    scatter_kernel<<<sb, 256>>>(h_p, ei, E);
    mlp_kernel<true><<<mb, 256>>>(h_p, W1_1, b1_1, W2_1, b2_1, nullptr, bat, fcW, N);

    final_kernel<<<1, 64>>>((float*)d_out, fcb);
}

// round 2
// speedup vs baseline: 1.2959x; 1.2959x over previous
#include <cuda_runtime.h>

#define N_NODES_MAX 100000
#define F 64
#define N_GRAPHS 64

// ---------------- scratch (static device globals; no allocs allowed) -------
__device__ float g_agg[(size_t)N_NODES_MAX * F];   // 25.6 MB, holds x + sum_neighbors
__device__ float g_h[(size_t)N_NODES_MAX * F];     // 25.6 MB
__device__ float g_sum[N_GRAPHS];
__device__ float g_cnt[N_GRAPHS];
__device__ int   g_e64;   // 1 if edge_index is int64, else int32
__device__ int   g_b64;   // 1 if batch is int64, else int32

// ---------------- packed f32x2 helpers (FFMA2 path, sm_103a) ---------------
__device__ __forceinline__ unsigned long long pack2(float a, float b) {
    unsigned long long r;
    asm("mov.b64 %0, {%1, %2};" : "=l"(r) : "f"(a), "f"(b));
    return r;
}
__device__ __forceinline__ unsigned long long splat2(float a) {
    unsigned long long r;
    asm("mov.b64 %0, {%1, %1};" : "=l"(r) : "f"(a));
    return r;
}
__device__ __forceinline__ void unpack2(unsigned long long v, float& a, float& b) {
    asm("mov.b64 {%0, %1}, %2;" : "=f"(a), "=f"(b) : "l"(v));
}
__device__ __forceinline__ unsigned long long ffma2(unsigned long long a,
                                                    unsigned long long b,
                                                    unsigned long long c) {
    unsigned long long r;
    asm("fma.rn.f32x2 %0, %1, %2, %3;" : "=l"(r) : "l"(a), "l"(b), "l"(c));
    return r;
}

// ---------------- dtype detection (int64 vs int32 indices) -----------------
__global__ void detect_kernel(const void* __restrict__ ei,
                              const void* __restrict__ batch, int nNodes) {
    if (threadIdx.x != 0 || blockIdx.x != 0) return;
    const long long* p = (const long long*)ei;
    bool ok = true;
    for (int i = 0; i < 4; i++) {
        long long v = p[i];
        if (v < 0 || v >= N_NODES_MAX) ok = false;
    }
    g_e64 = ok ? 1 : 0;
    const long long* q = (const long long*)batch;
    int M = nNodes / 2;
    bool okb = true;
    for (int i = M - 4; i < M; i++) {
        long long v = q[i];
        if (v < 0 || v >= N_GRAPHS) okb = false;
    }
    g_b64 = okb ? 1 : 0;
}

// ---------------- agg init: agg = x (folds the GIN "+x" term) --------------
__global__ void copy_init_kernel(const float* __restrict__ src, int n4) {
    int i = blockIdx.x * blockDim.x + threadIdx.x;
    if (i < n4) ((float4*)g_agg)[i] = ((const float4*)src)[i];
    if (blockIdx.x == 0 && threadIdx.x < N_GRAPHS) {
        g_sum[threadIdx.x] = 0.f;
        g_cnt[threadIdx.x] = 0.f;
    }
}

// ---------------- edge scatter-add: agg[dst] += feat[src] ------------------
// 16 threads per edge, one float4 each. Indices loaded ONCE per 16-group and
// broadcast with shfl (kills 320MB of redundant int64 index traffic).
__global__ void __launch_bounds__(256) scatter_kernel(
    const float* __restrict__ feat, const void* __restrict__ ei, int nE) {
    int t = blockIdx.x * 256 + threadIdx.x;
    int lane = threadIdx.x & 31;
    int e = t >> 4;
    int c = t & 15;
    bool valid = e < nE;
    int s = 0, d = 0;
    if (valid && (lane & 15) == 0) {
        if (g_e64) {
            const long long* p = (const long long*)ei;
            s = (int)p[e];
            d = (int)p[nE + e];
        } else {
            const int* p = (const int*)ei;
            s = p[e];
            d = p[nE + e];
        }
    }
    int srcl = lane & 16;  // first lane of this 16-group
    s = __shfl_sync(0xffffffffu, s, srcl);
    d = __shfl_sync(0xffffffffu, d, srcl);
    if (!valid) return;
    float4 v = *((const float4*)(feat + (size_t)s * F) + c);
    const float* dp = g_agg + (size_t)d * F + (size_t)c * 4;
    asm volatile("red.global.add.v4.f32 [%0], {%1, %2, %3, %4};"
                 :: "l"(dp), "f"(v.x), "f"(v.y), "f"(v.z), "f"(v.w)
                 : "memory");
}

// ---------------- batched 64->64 dense: 8 nodes per warp -------------------
// Lane owns outputs {2l, 2l+1} for all 8 nodes. Weights loaded from SMEM once
// per k and reused across the 8 nodes; inputs come as LDS.128 broadcasts.
__device__ __forceinline__ void dense64x8(
    const float* __restrict__ sW, unsigned long long bias,
    const float (*__restrict__ sx)[F], unsigned long long acc[8], int lane) {
#pragma unroll
    for (int nb = 0; nb < 8; nb++) acc[nb] = bias;
#pragma unroll
    for (int k4 = 0; k4 < 16; k4++) {
        const float* wr = sW + (k4 * 4) * F + 2 * lane;
        unsigned long long w0 = *(const unsigned long long*)(wr);
        unsigned long long w1 = *(const unsigned long long*)(wr + F);
        unsigned long long w2 = *(const unsigned long long*)(wr + 2 * F);
        unsigned long long w3 = *(const unsigned long long*)(wr + 3 * F);
#pragma unroll
        for (int nb = 0; nb < 8; nb++) {
            float4 iv = *(const float4*)&sx[nb][k4 * 4];
            acc[nb] = ffma2(w0, splat2(iv.x), acc[nb]);
            acc[nb] = ffma2(w1, splat2(iv.y), acc[nb]);
            acc[nb] = ffma2(w2, splat2(iv.z), acc[nb]);
            acc[nb] = ffma2(w3, splat2(iv.w), acc[nb]);
        }
    }
}

// ---------------- fused GIN MLP: out = relu(relu(agg@W1+b1)@W2+b2) ---------
// agg already contains x + sum_neighbors. POOL variant skips writing h and
// accumulates dot(h2, fcW) per graph.
template <bool POOL>
__global__ void __launch_bounds__(256) mlp_kernel(
    const float* __restrict__ W1, const float* __restrict__ b1,
    const float* __restrict__ W2, const float* __restrict__ b2,
    float* __restrict__ hout,
    const void* __restrict__ batch,
    const float* __restrict__ fcW,
    int nNodes) {
    __shared__ float sW1[F * F];                  // 16 KB
    __shared__ float sW2[F * F];                  // 16 KB
    __shared__ __align__(16) float sX[8][8][F];   // 16 KB: [warp][node][feat]

    int tid = threadIdx.x;
    for (int i = tid; i < F * F / 4; i += 256) {
        ((float4*)sW1)[i] = ((const float4*)W1)[i];
        ((float4*)sW2)[i] = ((const float4*)W2)[i];
    }
    __syncthreads();

    int warp = tid >> 5, lane = tid & 31;
    float(*sx)[F] = sX[warp];

    // per-thread small params from global (L1-cached, frees SMEM)
    float2 bv1 = *(const float2*)(b1 + 2 * lane);
    float2 bv2 = *(const float2*)(b2 + 2 * lane);
    unsigned long long bias1 = pack2(bv1.x, bv1.y);
    unsigned long long bias2 = pack2(bv2.x, bv2.y);
    float fc0 = 0.f, fc1 = 0.f;
    int b64 = 0;
    if (POOL) {
        float2 fv = *(const float2*)(fcW + 2 * lane);
        fc0 = fv.x; fc1 = fv.y;
        b64 = g_b64;
    }

    // 2 batches of 8 nodes per warp -> 128 nodes per block
    for (int it = 0; it < 2; it++) {
        int base = (blockIdx.x * 16 + warp * 2 + it) * 8;
        if (base >= nNodes) break;

        // Stage A: load 8 node rows (agg) into this warp's SMEM tile
#pragma unroll
        for (int i = 0; i < 4; i++) {
            int idx = lane + 32 * i;      // 0..127 float4 slots
            int nb = idx >> 4, c = idx & 15;
            int node = base + nb;
            float4 v = (node < nNodes)
                           ? *((const float4*)(g_agg + (size_t)node * F) + c)
                           : make_float4(0.f, 0.f, 0.f, 0.f);
            *(float4*)&sx[nb][c * 4] = v;
        }
        __syncwarp();

        unsigned long long acc[8];
        dense64x8(sW1, bias1, (const float(*)[F])sx, acc, lane);
        __syncwarp();
#pragma unroll
        for (int nb = 0; nb < 8; nb++) {
            float a, b;
            unpack2(acc[nb], a, b);
            *(float2*)&sx[nb][2 * lane] =
                make_float2(fmaxf(a, 0.f), fmaxf(b, 0.f));
        }
        __syncwarp();
        dense64x8(sW2, bias2, (const float(*)[F])sx, acc, lane);
        __syncwarp();

        if (POOL) {
#pragma unroll
            for (int nb = 0; nb < 8; nb++) {
                float a, b;
                unpack2(acc[nb], a, b);
                float s = fmaxf(a, 0.f) * fc0 + fmaxf(b, 0.f) * fc1;
#pragma unroll
                for (int o = 16; o > 0; o >>= 1)
                    s += __shfl_down_sync(0xffffffffu, s, o);
                if (lane == 0) {
                    int node = base + nb;
                    if (node < nNodes) {
                        int g = b64 ? (int)((const long long*)batch)[node]
                                    : ((const int*)batch)[node];
                        atomicAdd(&g_sum[g], s);
                        atomicAdd(&g_cnt[g], 1.f);
                    }
                }
            }
        } else {
#pragma unroll
            for (int nb = 0; nb < 8; nb++) {
                int node = base + nb;
                if (node < nNodes) {
                    float a, b;
                    unpack2(acc[nb], a, b);
                    *(float2*)&g_h[(size_t)node * F + 2 * lane] =
                        make_float2(fmaxf(a, 0.f), fmaxf(b, 0.f));
                }
            }
        }
    }
}

// ---------------- final: out[g] = sum/cnt + fcb -----------------------------
__global__ void final_kernel(float* __restrict__ out,
                             const float* __restrict__ fcb) {
    int g = threadIdx.x;
    if (g < N_GRAPHS)
        out[g] = g_sum[g] / fmaxf(g_cnt[g], 1.f) + fcb[0];
}

// ---------------- launch -----------------------------------------------------
extern "C" void kernel_launch(void* const* d_in, const int* in_sizes, int n_in,
                              void* d_out, int out_size) {
    const float* x    = (const float*)d_in[0];
    const void*  ei   = d_in[1];
    const void*  bat  = d_in[2];
    const float* W1_0 = (const float*)d_in[3];
    const float* b1_0 = (const float*)d_in[4];
    const float* W2_0 = (const float*)d_in[5];
    const float* b2_0 = (const float*)d_in[6];
    const float* W1_1 = (const float*)d_in[7];
    const float* b1_1 = (const float*)d_in[8];
    const float* W2_1 = (const float*)d_in[9];
    const float* b2_1 = (const float*)d_in[10];
    const float* fcW  = (const float*)d_in[11];
    const float* fcb  = (const float*)d_in[12];

    int E = in_sizes[1] / 2;
    int N = in_sizes[2];

    float* h_p = nullptr;
    cudaGetSymbolAddress((void**)&h_p, g_h);  // host-side, capture-safe

    int n4 = N * F / 4;
    int zb = (n4 + 255) / 256;
    long long sthreads = (long long)E * 16;
    int sb = (int)((sthreads + 255) / 256);
    int mb = (N + 127) / 128;

    detect_kernel<<<1, 32>>>(ei, bat, N);

    // ---- layer 1 ----
    copy_init_kernel<<<zb, 256>>>(x, n4);
    scatter_kernel<<<sb, 256>>>(x, ei, E);
    mlp_kernel<false><<<mb, 256>>>(W1_0, b1_0, W2_0, b2_0, h_p, bat, fcW, N);

    // ---- layer 2 (+ fused pooling projection) ----
    copy_init_kernel<<<zb, 256>>>(h_p, n4);
    scatter_kernel<<<sb, 256>>>(h_p, ei, E);
    mlp_kernel<true><<<mb, 256>>>(W1_1, b1_1, W2_1, b2_1, nullptr, bat, fcW, N);

    final_kernel<<<1, 64>>>((float*)d_out, fcb);
}

// round 3
// speedup vs baseline: 1.6072x; 1.2402x over previous
#include <cuda_runtime.h>

#define N_NODES_MAX 100000
#define N_EDGES_MAX 1300000
#define F 64
#define N_GRAPHS 64
#define SCAN_BS 512

// ---------------- scratch (static device globals; no allocs allowed) -------
__device__ float g_agg[(size_t)N_NODES_MAX * F];   // 25.6 MB
__device__ float g_h[(size_t)N_NODES_MAX * F];     // 25.6 MB
__device__ int   g_deg[N_NODES_MAX];
__device__ int   g_rowptr[N_NODES_MAX + 1];
__device__ int   g_cursor[N_NODES_MAX];
__device__ int   g_csr[N_EDGES_MAX];               // src ids grouped by dst
__device__ int   g_bsum[1024];
__device__ int   g_boff[1024];
__device__ float g_sum[N_GRAPHS];
__device__ float g_cnt[N_GRAPHS];
__device__ int   g_e64;   // 1 if edge_index is int64, else int32
__device__ int   g_b64;   // 1 if batch is int64, else int32

// ---------------- packed f32x2 helpers (FFMA2 path, sm_103a) ---------------
__device__ __forceinline__ unsigned long long pack2(float a, float b) {
    unsigned long long r;
    asm("mov.b64 %0, {%1, %2};" : "=l"(r) : "f"(a), "f"(b));
    return r;
}
__device__ __forceinline__ unsigned long long splat2(float a) {
    unsigned long long r;
    asm("mov.b64 %0, {%1, %1};" : "=l"(r) : "f"(a));
    return r;
}
__device__ __forceinline__ void unpack2(unsigned long long v, float& a, float& b) {
    asm("mov.b64 {%0, %1}, %2;" : "=f"(a), "=f"(b) : "l"(v));
}
__device__ __forceinline__ unsigned long long ffma2(unsigned long long a,
                                                    unsigned long long b,
                                                    unsigned long long c) {
    unsigned long long r;
    asm("fma.rn.f32x2 %0, %1, %2, %3;" : "=l"(r) : "l"(a), "l"(b), "l"(c));
    return r;
}

// ---------------- dtype detection (int64 vs int32 indices) -----------------
__global__ void detect_kernel(const void* __restrict__ ei,
                              const void* __restrict__ batch, int nNodes) {
    if (threadIdx.x != 0 || blockIdx.x != 0) return;
    const long long* p = (const long long*)ei;
    bool ok = true;
    for (int i = 0; i < 4; i++) {
        long long v = p[i];
        if (v < 0 || v >= N_NODES_MAX) ok = false;
    }
    g_e64 = ok ? 1 : 0;
    const long long* q = (const long long*)batch;
    int M = nNodes / 2;
    bool okb = true;
    for (int i = M - 4; i < M; i++) {
        long long v = q[i];
        if (v < 0 || v >= N_GRAPHS) okb = false;
    }
    g_b64 = okb ? 1 : 0;
}

// ---------------- CSR build ----------------------------------------------
__global__ void zero_deg_kernel(int nNodes) {
    int i = blockIdx.x * blockDim.x + threadIdx.x;
    if (i < nNodes) g_deg[i] = 0;
    if (i < N_GRAPHS) {
        g_sum[i] = 0.f;
        g_cnt[i] = 0.f;
    }
}

__global__ void hist_kernel(const void* __restrict__ ei, int nE) {
    int e = blockIdx.x * blockDim.x + threadIdx.x;
    if (e >= nE) return;
    int d;
    if (g_e64) d = (int)((const long long*)ei)[nE + e];
    else       d = ((const int*)ei)[nE + e];
    atomicAdd(&g_deg[d], 1);
}

// block partial sums of deg (SCAN_BS elems / block)
__global__ void __launch_bounds__(SCAN_BS) partial_kernel(int nNodes) {
    __shared__ int s[SCAN_BS];
    int i = blockIdx.x * SCAN_BS + threadIdx.x;
    s[threadIdx.x] = (i < nNodes) ? g_deg[i] : 0;
    __syncthreads();
    for (int o = SCAN_BS / 2; o > 0; o >>= 1) {
        if (threadIdx.x < o) s[threadIdx.x] += s[threadIdx.x + o];
        __syncthreads();
    }
    if (threadIdx.x == 0) g_bsum[blockIdx.x] = s[0];
}

// exclusive scan of block sums (single block, up to SCAN_BS blocks)
__global__ void __launch_bounds__(SCAN_BS) scanb_kernel(int nBlocks) {
    __shared__ int s[SCAN_BS];
    int t = threadIdx.x;
    int v = (t < nBlocks) ? g_bsum[t] : 0;
    s[t] = v;
    __syncthreads();
    for (int d = 1; d < SCAN_BS; d <<= 1) {
        int add = (t >= d) ? s[t - d] : 0;
        __syncthreads();
        s[t] += add;
        __syncthreads();
    }
    if (t < nBlocks) g_boff[t] = s[t] - v;  // exclusive
}

// per-chunk inclusive scan + offsets -> rowptr, cursor
__global__ void __launch_bounds__(SCAN_BS) scanf_kernel(int nNodes) {
    __shared__ int s[SCAN_BS];
    int t = threadIdx.x;
    int i = blockIdx.x * SCAN_BS + t;
    int v = (i < nNodes) ? g_deg[i] : 0;
    s[t] = v;
    __syncthreads();
    for (int d = 1; d < SCAN_BS; d <<= 1) {
        int add = (t >= d) ? s[t - d] : 0;
        __syncthreads();
        s[t] += add;
        __syncthreads();
    }
    if (i < nNodes) {
        int incl = g_boff[blockIdx.x] + s[t];
        g_rowptr[i + 1] = incl;
        g_cursor[i] = incl - v;
        if (i == 0) g_rowptr[0] = 0;
    }
}

__global__ void fill_kernel(const void* __restrict__ ei, int nE) {
    int e = blockIdx.x * blockDim.x + threadIdx.x;
    if (e >= nE) return;
    int sidx, d;
    if (g_e64) {
        const long long* p = (const long long*)ei;
        sidx = (int)p[e];
        d = (int)p[nE + e];
    } else {
        const int* p = (const int*)ei;
        sidx = p[e];
        d = p[nE + e];
    }
    int pos = atomicAdd(&g_cursor[d], 1);
    g_csr[pos] = sidx;
}

// ---------------- gather: out[i] = feat[i] + sum_{j in N(i)} feat[j] -------
// Warp per node; halves of warp process alternating edges; lane&15 = chunk.
__global__ void __launch_bounds__(256) gather_kernel(
    const float* __restrict__ feat, float* __restrict__ out, int nNodes) {
    int warp = threadIdx.x >> 5, lane = threadIdx.x & 31;
    int i = blockIdx.x * 8 + warp;
    if (i >= nNodes) return;
    int off = g_rowptr[i];
    int deg = g_rowptr[i + 1] - off;
    int half = lane >> 4, c = lane & 15;

    float4 acc;
    if (half == 0)
        acc = *((const float4*)(feat + (size_t)i * F) + c);
    else
        acc = make_float4(0.f, 0.f, 0.f, 0.f);

    for (int base = 0; base < deg; base += 32) {
        int cnt = min(deg - base, 32);
        int idx = 0;
        if (lane < cnt) idx = g_csr[off + base + lane];
        int iters = (cnt + 1) >> 1;
        for (int t = 0; t < iters; t++) {
            int k = 2 * t + half;
            int s = __shfl_sync(0xffffffffu, idx, k & 31);
            if (k < cnt) {
                float4 v = *((const float4*)(feat + (size_t)s * F) + c);
                acc.x += v.x; acc.y += v.y; acc.z += v.z; acc.w += v.w;
            }
        }
    }
    acc.x += __shfl_down_sync(0xffffffffu, acc.x, 16);
    acc.y += __shfl_down_sync(0xffffffffu, acc.y, 16);
    acc.z += __shfl_down_sync(0xffffffffu, acc.z, 16);
    acc.w += __shfl_down_sync(0xffffffffu, acc.w, 16);
    if (half == 0)
        *((float4*)(out + (size_t)i * F) + c) = acc;
}

// ---------------- batched 64->64 dense: 16 nodes per warp ------------------
__device__ __forceinline__ void dense64x16(
    const float* __restrict__ sW, unsigned long long bias,
    const float (*__restrict__ sx)[F], unsigned long long acc[16], int lane) {
#pragma unroll
    for (int nb = 0; nb < 16; nb++) acc[nb] = bias;
#pragma unroll 4
    for (int k4 = 0; k4 < 16; k4++) {
        const float* wr = sW + (k4 * 4) * F + 2 * lane;
        unsigned long long w0 = *(const unsigned long long*)(wr);
        unsigned long long w1 = *(const unsigned long long*)(wr + F);
        unsigned long long w2 = *(const unsigned long long*)(wr + 2 * F);
        unsigned long long w3 = *(const unsigned long long*)(wr + 3 * F);
#pragma unroll
        for (int nb = 0; nb < 16; nb++) {
            float4 iv = *(const float4*)&sx[nb][k4 * 4];
            acc[nb] = ffma2(w0, splat2(iv.x), acc[nb]);
            acc[nb] = ffma2(w1, splat2(iv.y), acc[nb]);
            acc[nb] = ffma2(w2, splat2(iv.z), acc[nb]);
            acc[nb] = ffma2(w3, splat2(iv.w), acc[nb]);
        }
    }
}

// ---------------- fused GIN MLP: out = relu(relu(in@W1+b1)@W2+b2) ----------
// 4 warps/block, 16 nodes per warp-batch, 2 batches -> 128 nodes per block.
template <bool POOL>
__global__ void __launch_bounds__(128) mlp_kernel(
    const float* __restrict__ xin,
    const float* __restrict__ W1, const float* __restrict__ b1,
    const float* __restrict__ W2, const float* __restrict__ b2,
    float* __restrict__ hout,
    const void* __restrict__ batch,
    const float* __restrict__ fcW,
    int nNodes) {
    __shared__ float sW1[F * F];                    // 16 KB
    __shared__ float sW2[F * F];                    // 16 KB
    __shared__ __align__(16) float sX[4][16][F];    // 16 KB

    int tid = threadIdx.x;
    for (int i = tid; i < F * F / 4; i += 128) {
        ((float4*)sW1)[i] = ((const float4*)W1)[i];
        ((float4*)sW2)[i] = ((const float4*)W2)[i];
    }
    __syncthreads();

    int warp = tid >> 5, lane = tid & 31;
    float(*sx)[F] = sX[warp];

    float2 bv1 = *(const float2*)(b1 + 2 * lane);
    float2 bv2 = *(const float2*)(b2 + 2 * lane);
    unsigned long long bias1 = pack2(bv1.x, bv1.y);
    unsigned long long bias2 = pack2(bv2.x, bv2.y);
    float fc0 = 0.f, fc1 = 0.f;
    int b64 = 0;
    if (POOL) {
        float2 fv = *(const float2*)(fcW + 2 * lane);
        fc0 = fv.x; fc1 = fv.y;
        b64 = g_b64;
    }

    for (int it = 0; it < 2; it++) {
        int base = (blockIdx.x * 8 + warp * 2 + it) * 16;
        if (base >= nNodes) break;

        // Stage A: load 16 node rows into this warp's SMEM tile
#pragma unroll
        for (int i = 0; i < 8; i++) {
            int idx = lane + 32 * i;  // 0..255 float4 slots
            int nb = idx >> 4, c = idx & 15;
            int node = base + nb;
            float4 v = (node < nNodes)
                           ? *((const float4*)(xin + (size_t)node * F) + c)
                           : make_float4(0.f, 0.f, 0.f, 0.f);
            *(float4*)&sx[nb][c * 4] = v;
        }
        __syncwarp();

        unsigned long long acc[16];
        dense64x16(sW1, bias1, (const float(*)[F])sx, acc, lane);
        __syncwarp();
#pragma unroll
        for (int nb = 0; nb < 16; nb++) {
            float a, b;
            unpack2(acc[nb], a, b);
            *(float2*)&sx[nb][2 * lane] =
                make_float2(fmaxf(a, 0.f), fmaxf(b, 0.f));
        }
        __syncwarp();
        dense64x16(sW2, bias2, (const float(*)[F])sx, acc, lane);
        __syncwarp();

        if (POOL) {
#pragma unroll
            for (int nb = 0; nb < 16; nb++) {
                float a, b;
                unpack2(acc[nb], a, b);
                float s = fmaxf(a, 0.f) * fc0 + fmaxf(b, 0.f) * fc1;
#pragma unroll
                for (int o = 16; o > 0; o >>= 1)
                    s += __shfl_down_sync(0xffffffffu, s, o);
                if (lane == 0) {
                    int node = base + nb;
                    if (node < nNodes) {
                        int g = b64 ? (int)((const long long*)batch)[node]
                                    : ((const int*)batch)[node];
                        atomicAdd(&g_sum[g], s);
                        atomicAdd(&g_cnt[g], 1.f);
                    }
                }
            }
        } else {
#pragma unroll
            for (int nb = 0; nb < 16; nb++) {
                int node = base + nb;
                if (node < nNodes) {
                    float a, b;
                    unpack2(acc[nb], a, b);
                    *(float2*)&hout[(size_t)node * F + 2 * lane] =
                        make_float2(fmaxf(a, 0.f), fmaxf(b, 0.f));
                }
            }
        }
    }
}

// ---------------- final: out[g] = sum/cnt + fcb -----------------------------
__global__ void final_kernel(float* __restrict__ out,
                             const float* __restrict__ fcb) {
    int g = threadIdx.x;
    if (g < N_GRAPHS)
        out[g] = g_sum[g] / fmaxf(g_cnt[g], 1.f) + fcb[0];
}

// ---------------- launch -----------------------------------------------------
extern "C" void kernel_launch(void* const* d_in, const int* in_sizes, int n_in,
                              void* d_out, int out_size) {
    const float* x    = (const float*)d_in[0];
    const void*  ei   = d_in[1];
    const void*  bat  = d_in[2];
    const float* W1_0 = (const float*)d_in[3];
    const float* b1_0 = (const float*)d_in[4];
    const float* W2_0 = (const float*)d_in[5];
    const float* b2_0 = (const float*)d_in[6];
    const float* W1_1 = (const float*)d_in[7];
    const float* b1_1 = (const float*)d_in[8];
    const float* W2_1 = (const float*)d_in[9];
    const float* b2_1 = (const float*)d_in[10];
    const float* fcW  = (const float*)d_in[11];
    const float* fcb  = (const float*)d_in[12];

    int E = in_sizes[1] / 2;
    int N = in_sizes[2];

    float *agg_p = nullptr, *h_p = nullptr;
    cudaGetSymbolAddress((void**)&agg_p, g_agg);
    cudaGetSymbolAddress((void**)&h_p, g_h);

    int eb = (E + 255) / 256;
    int nb = (N + 255) / 256;
    int sblocks = (N + SCAN_BS - 1) / SCAN_BS;
    int gb = (N + 7) / 8;
    int mb = (N + 127) / 128;

    // ---- CSR build (shared by both layers) ----
    detect_kernel<<<1, 32>>>(ei, bat, N);
    zero_deg_kernel<<<nb, 256>>>(N);
    hist_kernel<<<eb, 256>>>(ei, E);
    partial_kernel<<<sblocks, SCAN_BS>>>(N);
    scanb_kernel<<<1, SCAN_BS>>>(sblocks);
    scanf_kernel<<<sblocks, SCAN_BS>>>(N);
    fill_kernel<<<eb, 256>>>(ei, E);

    // ---- layer 1 ----
    gather_kernel<<<gb, 256>>>(x, agg_p, N);
    mlp_kernel<false><<<mb, 128>>>(agg_p, W1_0, b1_0, W2_0, b2_0, h_p, bat, fcW, N);

    // ---- layer 2 (+ fused pooling projection) ----
    gather_kernel<<<gb, 256>>>(h_p, agg_p, N);
    mlp_kernel<true><<<mb, 128>>>(agg_p, W1_1, b1_1, W2_1, b2_1, nullptr, bat, fcW, N);

    final_kernel<<<1, 64>>>((float*)d_out, fcb);
}